// round 4
// baseline (speedup 1.0000x reference)
#include <cuda_runtime.h>
#include <stdint.h>

#define S 8192
#define D 4096
#define E 64
#define CAP 128

#define BT 32
#define KC 64
#define GEMM_THREADS 128

// output layout: [ l_aux (1) | combine (S*E*CAP) | dispatch (S*E*CAP) | exp_counts (E) ]
#define SEC ((size_t)S * E * CAP)
#define OFF_COMBINE ((size_t)1)
#define OFF_DISPATCH ((size_t)1 + SEC)
#define OFF_CNT ((size_t)1 + 2 * SEC)

// scratch (device globals: no allocation allowed)
__device__ float g_sel_gate[S];
__device__ int g_sel_idx[S];
__device__ int g_slots[S];
__device__ float g_me_sum[E];
__device__ int g_cnt[E];

__global__ void init_kernel() {
    int t = threadIdx.x;
    if (t < E) g_me_sum[t] = 0.f;
}

// ---------------------------------------------------------------------------
// Fused gate GEMM + softmax + argmax + per-expert gate-mean partial reduction.
// C[S,E] = x[S,D] @ w[E,D]^T, fp32. Block: 32 tokens x 64 experts, K-chunk 64.
// 128 threads, each computes a 4x4 register tile (4 tokens x 4 experts).
// ---------------------------------------------------------------------------
__global__ __launch_bounds__(GEMM_THREADS) void gate_gemm_kernel(
    const float* __restrict__ x, const float* __restrict__ w) {
    __shared__ float xs[BT][KC + 1];   // also reused for logits [BT][E]
    __shared__ float ws[E][KC + 1];
    __shared__ float s_max[BT];
    __shared__ float s_inv[BT];

    const int tid = threadIdx.x;
    const int tx = tid & 15;   // expert group (4 experts each)
    const int ty = tid >> 4;   // token group (4 tokens each)
    const int t0 = blockIdx.x * BT;

    float acc[4][4];
#pragma unroll
    for (int i = 0; i < 4; i++)
#pragma unroll
        for (int j = 0; j < 4; j++) acc[i][j] = 0.f;

    for (int kc = 0; kc < D; kc += KC) {
        // x tile: 32 rows x 64 cols = 512 float4, 4 per thread
#pragma unroll
        for (int l = 0; l < 4; l++) {
            int f4 = tid + l * GEMM_THREADS;
            int row = f4 >> 4;
            int c4 = f4 & 15;
            float4 v = *reinterpret_cast<const float4*>(
                &x[(size_t)(t0 + row) * D + kc + c4 * 4]);
            xs[row][c4 * 4 + 0] = v.x;
            xs[row][c4 * 4 + 1] = v.y;
            xs[row][c4 * 4 + 2] = v.z;
            xs[row][c4 * 4 + 3] = v.w;
        }
        // w tile: 64 rows x 64 cols = 1024 float4, 8 per thread
#pragma unroll
        for (int l = 0; l < 8; l++) {
            int f4 = tid + l * GEMM_THREADS;
            int row = f4 >> 4;
            int c4 = f4 & 15;
            float4 v = *reinterpret_cast<const float4*>(
                &w[(size_t)row * D + kc + c4 * 4]);
            ws[row][c4 * 4 + 0] = v.x;
            ws[row][c4 * 4 + 1] = v.y;
            ws[row][c4 * 4 + 2] = v.z;
            ws[row][c4 * 4 + 3] = v.w;
        }
        __syncthreads();
#pragma unroll
        for (int kk = 0; kk < KC; kk++) {
            float xv[4], wv[4];
#pragma unroll
            for (int i = 0; i < 4; i++) xv[i] = xs[4 * ty + i][kk];
#pragma unroll
            for (int j = 0; j < 4; j++) wv[j] = ws[4 * tx + j][kk];
#pragma unroll
            for (int i = 0; i < 4; i++)
#pragma unroll
                for (int j = 0; j < 4; j++) acc[i][j] += xv[i] * wv[j];
        }
        __syncthreads();
    }

    // logits -> smem (reuse xs: [32][65] holds [32][64])
#pragma unroll
    for (int i = 0; i < 4; i++)
#pragma unroll
        for (int j = 0; j < 4; j++) xs[4 * ty + i][4 * tx + j] = acc[i][j];
    __syncthreads();

    // per-token softmax + argmax (first-max tie-break like jnp.argmax)
    if (tid < BT) {
        const int t = tid;
        float m = xs[t][0];
        int am = 0;
#pragma unroll
        for (int e = 1; e < E; e++) {
            float v = xs[t][e];
            if (v > m) { m = v; am = e; }
        }
        float ssum = 0.f;
#pragma unroll
        for (int e = 0; e < E; e++) ssum += expf(xs[t][e] - m);
        float inv = 1.0f / ssum;
        s_max[t] = m;
        s_inv[t] = inv;
        g_sel_gate[t0 + t] = inv;  // gate at argmax = exp(0)/sum
        g_sel_idx[t0 + t] = am;
    }
    __syncthreads();

    // per-expert partial column sums of gates (for me / l_aux)
    if (tid < E) {
        const int e = tid;
        float cs = 0.f;
#pragma unroll
        for (int t = 0; t < BT; t++) cs += expf(xs[t][e] - s_max[t]) * s_inv[t];
        atomicAdd(&g_me_sum[e], cs);
    }
}

// ---------------------------------------------------------------------------
// Per-expert: count assigned, exact 128th-largest-noise threshold (bitwise
// binary search; fp32 in [0,1) so uint bit order == float order), then
// ordered block-scan to assign capacity slots.
// ---------------------------------------------------------------------------
#define BUF 5120
#define ETHREADS 256

__global__ __launch_bounds__(ETHREADS) void expert_kernel(
    const float* __restrict__ noise, float* __restrict__ out) {
    __shared__ uint32_t sbuf[BUF];
    __shared__ int scnt;
    __shared__ int sred;
    __shared__ int swsum[ETHREADS / 32];

    const int e = blockIdx.x;
    const int tid = threadIdx.x;
    const int lane = tid & 31;
    const int wid = tid >> 5;

    if (tid == 0) scnt = 0;
    __syncthreads();

    // gather assigned noises into smem (order irrelevant for threshold)
    for (int t = tid; t < S; t += ETHREADS) {
        if (g_sel_idx[t] == e) {
            int p = atomicAdd(&scnt, 1);
            if (p < BUF) sbuf[p] = __float_as_uint(noise[(size_t)t * E + e]);
        }
    }
    __syncthreads();
    const int cnt = scnt;
    if (tid == 0) {
        g_cnt[e] = cnt;
        out[OFF_CNT + e] = (float)cnt;
    }

    // threshold V = bits of the CAP-th largest noise (kept iff bits >= V)
    uint32_t V = 0;
    if (cnt > CAP) {
        const bool use_smem = (cnt <= BUF);
        for (int bit = 31; bit >= 0; bit--) {
            uint32_t trial = V | (1u << bit);
            int c = 0;
            if (use_smem) {
                for (int i = tid; i < cnt; i += ETHREADS)
                    c += (sbuf[i] >= trial) ? 1 : 0;
            } else {  // pathological skew fallback (never expected)
                for (int t = tid; t < S; t += ETHREADS)
                    c += (g_sel_idx[t] == e &&
                          __float_as_uint(noise[(size_t)t * E + e]) >= trial)
                             ? 1
                             : 0;
            }
#pragma unroll
            for (int off = 16; off; off >>= 1)
                c += __shfl_down_sync(0xffffffffu, c, off);
            __syncthreads();
            if (tid == 0) sred = 0;
            __syncthreads();
            if (lane == 0) atomicAdd(&sred, c);
            __syncthreads();
            if (sred >= CAP) V = trial;
        }
    }

    // ordered scan over tokens -> capacity slot (== per-expert cumsum - 1)
    int running = 0;
    for (int base = 0; base < S; base += ETHREADS) {
        int t = base + tid;
        bool assigned = (g_sel_idx[t] == e);
        bool kept = assigned &&
                    (__float_as_uint(noise[(size_t)t * E + e]) >= V);
        unsigned m = __ballot_sync(0xffffffffu, kept);
        int pre = __popc(m & ((1u << lane) - 1u));
        if (lane == 0) swsum[wid] = __popc(m);
        __syncthreads();
        int wbase = 0;
#pragma unroll
        for (int ww = 0; ww < ETHREADS / 32; ww++) {
            if (ww < wid) wbase += swsum[ww];
        }
        int tot = 0;
#pragma unroll
        for (int ww = 0; ww < ETHREADS / 32; ww++) tot += swsum[ww];
        if (assigned) g_slots[t] = kept ? (running + wbase + pre) : -1;
        running += tot;
        __syncthreads();
    }
}

// ---------------------------------------------------------------------------
// Finalize: scatter combine/dispatch nonzeros; compute l_aux.
// ---------------------------------------------------------------------------
__global__ __launch_bounds__(256) void finalize_kernel(float* __restrict__ out) {
    const int b = blockIdx.x;
    const int tid = threadIdx.x;
    if (b < S / 256) {
        int t = b * 256 + tid;
        int s = g_slots[t];
        if (s >= 0) {
            int e = g_sel_idx[t];
            size_t base = OFF_COMBINE + (((size_t)t * E + e) * CAP + (size_t)s);
            out[base] = g_sel_gate[t];
            out[base + SEC] = 1.0f;
        }
    } else {
        __shared__ float red[2];
        float v = 0.f;
        if (tid < E) v = g_me_sum[tid] * (float)g_cnt[tid];
#pragma unroll
        for (int off = 16; off; off >>= 1)
            v += __shfl_down_sync(0xffffffffu, v, off);
        if (tid == 0) red[0] = v;
        if (tid == 32) red[1] = v;
        __syncthreads();
        if (tid == 0)
            out[0] = (red[0] + red[1]) * ((float)E / ((float)S * (float)S));
    }
}

extern "C" void kernel_launch(void* const* d_in, const int* in_sizes, int n_in,
                              void* d_out, int out_size) {
    const float* x = (const float*)d_in[0];        // [S, D]
    const float* w = (const float*)d_in[1];        // [E, D]
    const float* noise = (const float*)d_in[2];    // [S, E]
    float* out = (float*)d_out;

    cudaMemsetAsync(d_out, 0, (size_t)out_size * sizeof(float), 0);
    init_kernel<<<1, 64>>>();
    gate_gemm_kernel<<<S / BT, GEMM_THREADS>>>(x, w);
    expert_kernel<<<E, ETHREADS>>>(noise, out);
    finalize_kernel<<<S / 256 + 1, 256>>>(out);
}

// round 5
// speedup vs baseline: 1.1444x; 1.1444x over previous
#include <cuda_runtime.h>
#include <stdint.h>

#define S 8192
#define D 4096
#define E 64
#define CAP 128

#define BT 64            // tokens per gemm block
#define KC 64            // k-chunk
#define GT 256           // gemm threads per block
#define NBLK (S / BT)    // 128 gemm blocks = one wave on 152 SMs
#define NCHUNK (D / KC)  // 64

// output layout: [ l_aux (1) | combine (S*E*CAP) | dispatch (S*E*CAP) | exp_counts (E) ]
#define SEC ((size_t)S * E * CAP)
#define OFF_COMBINE ((size_t)1)
#define OFF_CNT ((size_t)1 + 2 * SEC)

// scratch (device globals: no allocation allowed)
__device__ float g_sel_gate[S];
__device__ int g_sel_idx[S];
__device__ int g_slots[S];
__device__ float g_me_part[NBLK][E];
__device__ int g_cnt[E];

// ---------------------------------------------------------------------------
// Fused: gate GEMM (fp32) + softmax + argmax + per-expert gate-mean partials
//        + interleaved zero-fill of the whole output buffer (overlaps DRAM
//          writes with the FMA-bound mainloop).
// Block: 64 tokens x 64 experts, 256 threads, 4x4 register tile each.
// SMEM tiles are kk-major with an XOR-16B-group swizzle so the mainloop uses
// LDS.128 (x: broadcast, w: 2 wavefronts) and STS stays 2-way.
// ---------------------------------------------------------------------------
__global__ __launch_bounds__(GT) void gate_gemm_kernel(
    const float* __restrict__ x, const float* __restrict__ w,
    float* __restrict__ out, int out_elems) {
    __shared__ float pool[KC * BT + KC * E];  // xs then ws; reused for logits
    __shared__ float s_max[BT];
    __shared__ float s_inv[BT];

    float* xs = pool;            // [KC][BT] swizzled
    float* ws = pool + KC * BT;  // [KC][E]  swizzled

    const int tid = threadIdx.x;
    const int b = blockIdx.x;
    const int tx = tid & 15;   // expert group (experts 4tx..4tx+3)
    const int ty = tid >> 4;   // token group (tokens 4ty..4ty+3)
    const int t0 = b * BT;

    // ---- zero-fill bookkeeping (out poisoned; we own the memset) ----
    const unsigned n4 = (unsigned)(out_elems >> 2);
    const unsigned per = (n4 + NBLK - 1) / NBLK;           // 262145
    const unsigned z0 = (unsigned)b * per;
    const unsigned z1 = (z0 + per < n4) ? (z0 + per) : n4;
    float4* out4 = (float4*)out;
    const float4 zz = make_float4(0.f, 0.f, 0.f, 0.f);

    float acc[4][4];
#pragma unroll
    for (int i = 0; i < 4; i++)
#pragma unroll
        for (int j = 0; j < 4; j++) acc[i][j] = 0.f;

    float4 xr[4], wr[4];
    // prefetch chunk 0 into registers
#pragma unroll
    for (int l = 0; l < 4; l++) {
        int f4 = tid + l * GT;
        int row = f4 >> 4;
        int c4 = f4 & 15;
        xr[l] = *reinterpret_cast<const float4*>(&x[(size_t)(t0 + row) * D + c4 * 4]);
        wr[l] = *reinterpret_cast<const float4*>(&w[(size_t)row * D + c4 * 4]);
    }

    for (int ch = 0; ch < NCHUNK; ch++) {
        // ---- store regs -> swizzled smem ----
#pragma unroll
        for (int l = 0; l < 4; l++) {
            int f4 = tid + l * GT;
            int row = f4 >> 4;   // token / expert
            int c4 = f4 & 15;
            int rg = row >> 2;   // 16B group of row
            int rr = row & 3;
            float v[4] = {xr[l].x, xr[l].y, xr[l].z, xr[l].w};
            float u[4] = {wr[l].x, wr[l].y, wr[l].z, wr[l].w};
#pragma unroll
            for (int j = 0; j < 4; j++) {
                int kk = 4 * c4 + j;               // kk>>2 == c4
                int sidx = kk * 64 + ((rg ^ c4) & 15) * 4 + rr;
                xs[sidx] = v[j];
                ws[sidx] = u[j];
            }
        }
        __syncthreads();

        // ---- prefetch next chunk ----
        if (ch + 1 < NCHUNK) {
            int kc = (ch + 1) * KC;
#pragma unroll
            for (int l = 0; l < 4; l++) {
                int f4 = tid + l * GT;
                int row = f4 >> 4;
                int c4 = f4 & 15;
                xr[l] = *reinterpret_cast<const float4*>(
                    &x[(size_t)(t0 + row) * D + kc + c4 * 4]);
                wr[l] = *reinterpret_cast<const float4*>(
                    &w[(size_t)row * D + kc + c4 * 4]);
            }
        }

        // ---- interleaved zero-fill slice (DRAM overlaps FMA) ----
#pragma unroll
        for (int k = 0; k < 17; k++) {
            unsigned idx = z0 + ((unsigned)ch * 17 + k) * GT + tid;
            if (idx < z1) out4[idx] = zz;
        }

        // ---- mainloop: FMA-bound ----
#pragma unroll 8
        for (int kk = 0; kk < KC; kk++) {
            int kg = kk >> 2;
            float4 xv = *reinterpret_cast<const float4*>(
                &xs[kk * 64 + ((ty ^ kg) & 15) * 4]);
            float4 wv = *reinterpret_cast<const float4*>(
                &ws[kk * 64 + ((tx ^ kg) & 15) * 4]);
            float xa[4] = {xv.x, xv.y, xv.z, xv.w};
            float wa[4] = {wv.x, wv.y, wv.z, wv.w};
#pragma unroll
            for (int i = 0; i < 4; i++)
#pragma unroll
                for (int j = 0; j < 4; j++) acc[i][j] += xa[i] * wa[j];
        }
        __syncthreads();
    }

    // tail floats beyond 16B granularity (out_elems % 4)
    if (b == 0) {
        for (int i = (int)(n4 << 2) + tid; i < out_elems; i += GT) out[i] = 0.f;
    }

    // ---- logits -> smem (reuse pool as ls[BT][E+1], padded: conflict-free) ----
    float(*ls)[E + 1] = (float(*)[E + 1])pool;
#pragma unroll
    for (int i = 0; i < 4; i++)
#pragma unroll
        for (int j = 0; j < 4; j++) ls[4 * ty + i][4 * tx + j] = acc[i][j];
    __syncthreads();

    // per-token softmax + argmax (first-max tie-break like jnp.argmax)
    if (tid < BT) {
        const int t = tid;
        float m = ls[t][0];
        int am = 0;
#pragma unroll
        for (int e = 1; e < E; e++) {
            float v = ls[t][e];
            if (v > m) { m = v; am = e; }
        }
        float ssum = 0.f;
#pragma unroll
        for (int e = 0; e < E; e++) ssum += expf(ls[t][e] - m);
        float inv = 1.0f / ssum;
        s_max[t] = m;
        s_inv[t] = inv;
        g_sel_gate[t0 + t] = inv;  // gate at argmax = exp(0)/sum
        g_sel_idx[t0 + t] = am;
    }
    __syncthreads();

    // per-expert partial column sums of gates (for me / l_aux)
    if (tid < E) {
        const int e = tid;
        float cs = 0.f;
#pragma unroll
        for (int t = 0; t < BT; t++) cs += expf(ls[t][e] - s_max[t]) * s_inv[t];
        g_me_part[b][e] = cs;
    }
}

// ---------------------------------------------------------------------------
// Per-expert: count assigned, exact 128th-largest-noise threshold (bitwise
// binary search; fp32 in [0,1) so uint bit order == float order), then
// ordered block-scan to assign capacity slots.
// ---------------------------------------------------------------------------
#define BUF 5120
#define ETHREADS 256

__global__ __launch_bounds__(ETHREADS) void expert_kernel(
    const float* __restrict__ noise, float* __restrict__ out) {
    __shared__ uint32_t sbuf[BUF];
    __shared__ int scnt;
    __shared__ int sred;
    __shared__ int swsum[ETHREADS / 32];

    const int e = blockIdx.x;
    const int tid = threadIdx.x;
    const int lane = tid & 31;
    const int wid = tid >> 5;

    if (tid == 0) scnt = 0;
    __syncthreads();

    // gather assigned noises into smem (order irrelevant for threshold)
    for (int t = tid; t < S; t += ETHREADS) {
        if (g_sel_idx[t] == e) {
            int p = atomicAdd(&scnt, 1);
            if (p < BUF) sbuf[p] = __float_as_uint(noise[(size_t)t * E + e]);
        }
    }
    __syncthreads();
    const int cnt = scnt;
    if (tid == 0) {
        g_cnt[e] = cnt;
        out[OFF_CNT + e] = (float)cnt;
    }

    // threshold V = bits of the CAP-th largest noise (kept iff bits >= V)
    uint32_t V = 0;
    if (cnt > CAP) {
        const bool use_smem = (cnt <= BUF);
        for (int bit = 31; bit >= 0; bit--) {
            uint32_t trial = V | (1u << bit);
            int c = 0;
            if (use_smem) {
                for (int i = tid; i < cnt; i += ETHREADS)
                    c += (sbuf[i] >= trial) ? 1 : 0;
            } else {  // pathological skew fallback (never expected)
                for (int t = tid; t < S; t += ETHREADS)
                    c += (g_sel_idx[t] == e &&
                          __float_as_uint(noise[(size_t)t * E + e]) >= trial)
                             ? 1
                             : 0;
            }
#pragma unroll
            for (int off = 16; off; off >>= 1)
                c += __shfl_down_sync(0xffffffffu, c, off);
            __syncthreads();
            if (tid == 0) sred = 0;
            __syncthreads();
            if (lane == 0) atomicAdd(&sred, c);
            __syncthreads();
            if (sred >= CAP) V = trial;
        }
    }

    // ordered scan over tokens -> capacity slot (== per-expert cumsum - 1)
    int running = 0;
    for (int base = 0; base < S; base += ETHREADS) {
        int t = base + tid;
        bool assigned = (g_sel_idx[t] == e);
        bool kept = assigned &&
                    (__float_as_uint(noise[(size_t)t * E + e]) >= V);
        unsigned m = __ballot_sync(0xffffffffu, kept);
        int pre = __popc(m & ((1u << lane) - 1u));
        if (lane == 0) swsum[wid] = __popc(m);
        __syncthreads();
        int wbase = 0;
#pragma unroll
        for (int ww = 0; ww < ETHREADS / 32; ww++) {
            if (ww < wid) wbase += swsum[ww];
        }
        int tot = 0;
#pragma unroll
        for (int ww = 0; ww < ETHREADS / 32; ww++) tot += swsum[ww];
        if (assigned) g_slots[t] = kept ? (running + wbase + pre) : -1;
        running += tot;
        __syncthreads();
    }
}

// ---------------------------------------------------------------------------
// Finalize: scatter combine/dispatch nonzeros; compute l_aux.
// ---------------------------------------------------------------------------
__global__ __launch_bounds__(256) void finalize_kernel(float* __restrict__ out) {
    const int b = blockIdx.x;
    const int tid = threadIdx.x;
    if (b < S / 256) {
        int t = b * 256 + tid;
        int s = g_slots[t];
        if (s >= 0) {
            int e = g_sel_idx[t];
            size_t base = OFF_COMBINE + (((size_t)t * E + e) * CAP + (size_t)s);
            out[base] = g_sel_gate[t];
            out[base + SEC] = 1.0f;
        }
    } else {
        __shared__ float red[2];
        float v = 0.f;
        if (tid < E) {
            float ms = 0.f;
            for (int p = 0; p < NBLK; p++) ms += g_me_part[p][tid];
            v = ms * (float)g_cnt[tid];
        }
#pragma unroll
        for (int off = 16; off; off >>= 1)
            v += __shfl_down_sync(0xffffffffu, v, off);
        if (tid == 0) red[0] = v;
        if (tid == 32) red[1] = v;
        __syncthreads();
        if (tid == 0)
            out[0] = (red[0] + red[1]) * ((float)E / ((float)S * (float)S));
    }
}

extern "C" void kernel_launch(void* const* d_in, const int* in_sizes, int n_in,
                              void* d_out, int out_size) {
    const float* x = (const float*)d_in[0];      // [S, D]
    const float* w = (const float*)d_in[1];      // [E, D]
    const float* noise = (const float*)d_in[2];  // [S, E]
    float* out = (float*)d_out;

    gate_gemm_kernel<<<NBLK, GT>>>(x, w, out, out_size);
    expert_kernel<<<E, ETHREADS>>>(noise, out);
    finalize_kernel<<<S / 256 + 1, 256>>>(out);
}

// round 6
// speedup vs baseline: 1.1476x; 1.0027x over previous
#include <cuda_runtime.h>
#include <stdint.h>

#define S 8192
#define D 4096
#define E 64
#define CAP 128

#define BT 64            // tokens per gemm block
#define KC 64            // k-chunk
#define GT 256           // gemm threads per block
#define NBLK (S / BT)    // 128 gemm blocks
#define NCHUNK (D / KC)  // 64

// output layout: [ l_aux (1) | combine (S*E*CAP) | dispatch (S*E*CAP) | exp_counts (E) ]
#define SEC ((size_t)S * E * CAP)
#define OFF_COMBINE ((size_t)1)
#define OFF_CNT ((size_t)1 + 2 * SEC)

// scratch (device globals: no allocation allowed)
__device__ float g_sel_gate[S];
__device__ int g_sel_idx[S];
__device__ float g_me_part[NBLK][E];
__device__ int g_cnt[E];

// ---- packed fp32x2 helpers (FFMA2 path; fma pipe issues 2 FLOPs/inst) ----
__device__ __forceinline__ void fma2(unsigned long long& d, unsigned long long a,
                                     unsigned long long b) {
    asm("fma.rn.f32x2 %0, %1, %2, %0;" : "+l"(d) : "l"(a), "l"(b));
}
__device__ __forceinline__ unsigned long long pack2(float lo, float hi) {
    unsigned long long r;
    asm("mov.b64 %0, {%1, %2};" : "=l"(r) : "f"(lo), "f"(hi));
    return r;
}
__device__ __forceinline__ void unpack2(unsigned long long v, float& lo, float& hi) {
    asm("mov.b64 {%0, %1}, %2;" : "=f"(lo), "=f"(hi) : "l"(v));
}

// ---------------------------------------------------------------------------
// Fused: gate GEMM (fp32, FFMA2 inner product) + softmax + argmax +
//        per-expert gate-mean partials + interleaved zero-fill of the output.
// Block: 64 tokens x 64 experts, 256 threads; each thread owns a 4x4 tile
// held as 2 token-pairs x 4 experts of f32x2 accumulators (token pairing =>
// summation order identical to scalar version; no extra argmax risk).
// ---------------------------------------------------------------------------
__global__ __launch_bounds__(GT) void gate_gemm_kernel(
    const float* __restrict__ x, const float* __restrict__ w,
    float* __restrict__ out, int out_elems) {
    __shared__ float pool[KC * BT + KC * E];  // xs then ws; reused for logits
    __shared__ float s_max[BT];
    __shared__ float s_inv[BT];

    float* xs = pool;            // [KC][BT] swizzled (kk-major)
    float* ws = pool + KC * BT;  // [KC][E]  swizzled

    const int tid = threadIdx.x;
    const int b = blockIdx.x;
    const int tx = tid & 15;   // expert group (experts 4tx..4tx+3)
    const int ty = tid >> 4;   // token group (tokens 4ty..4ty+3)
    const int t0 = b * BT;

    // ---- zero-fill bookkeeping (out poisoned; we own the memset) ----
    const unsigned n4 = (unsigned)(out_elems >> 2);
    const unsigned per = (n4 + NBLK - 1) / NBLK;
    const unsigned z0 = (unsigned)b * per;
    const unsigned z1 = (z0 + per < n4) ? (z0 + per) : n4;
    float4* out4 = (float4*)out;
    const float4 zz = make_float4(0.f, 0.f, 0.f, 0.f);

    unsigned long long acc2[2][4];  // [token-pair][expert]
#pragma unroll
    for (int p = 0; p < 2; p++)
#pragma unroll
        for (int j = 0; j < 4; j++) acc2[p][j] = 0ull;

    float4 xr[4], wr[4];
    // prefetch chunk 0 into registers
#pragma unroll
    for (int l = 0; l < 4; l++) {
        int f4 = tid + l * GT;
        int row = f4 >> 4;
        int c4 = f4 & 15;
        xr[l] = *reinterpret_cast<const float4*>(&x[(size_t)(t0 + row) * D + c4 * 4]);
        wr[l] = *reinterpret_cast<const float4*>(&w[(size_t)row * D + c4 * 4]);
    }

    for (int ch = 0; ch < NCHUNK; ch++) {
        // ---- store regs -> swizzled smem ----
#pragma unroll
        for (int l = 0; l < 4; l++) {
            int f4 = tid + l * GT;
            int row = f4 >> 4;  // token / expert
            int c4 = f4 & 15;
            int rg = row >> 2;  // 16B group of row
            int rr = row & 3;
            float v[4] = {xr[l].x, xr[l].y, xr[l].z, xr[l].w};
            float u[4] = {wr[l].x, wr[l].y, wr[l].z, wr[l].w};
#pragma unroll
            for (int j = 0; j < 4; j++) {
                int kk = 4 * c4 + j;  // kk>>2 == c4
                int sidx = kk * 64 + ((rg ^ c4) & 15) * 4 + rr;
                xs[sidx] = v[j];
                ws[sidx] = u[j];
            }
        }
        __syncthreads();

        // ---- prefetch next chunk ----
        if (ch + 1 < NCHUNK) {
            int kc = (ch + 1) * KC;
#pragma unroll
            for (int l = 0; l < 4; l++) {
                int f4 = tid + l * GT;
                int row = f4 >> 4;
                int c4 = f4 & 15;
                xr[l] = *reinterpret_cast<const float4*>(
                    &x[(size_t)(t0 + row) * D + kc + c4 * 4]);
                wr[l] = *reinterpret_cast<const float4*>(
                    &w[(size_t)row * D + kc + c4 * 4]);
            }
        }

        // ---- interleaved zero-fill slice (DRAM overlaps FMA) ----
#pragma unroll
        for (int k = 0; k < 17; k++) {
            unsigned idx = z0 + ((unsigned)ch * 17 + k) * GT + tid;
            if (idx < z1) out4[idx] = zz;
        }

        // ---- mainloop: FFMA2 ----
#pragma unroll 8
        for (int kk = 0; kk < KC; kk++) {
            int kg = kk >> 2;
            float4 xv = *reinterpret_cast<const float4*>(
                &xs[kk * 64 + ((ty ^ kg) & 15) * 4]);
            float4 wv = *reinterpret_cast<const float4*>(
                &ws[kk * 64 + ((tx ^ kg) & 15) * 4]);
            unsigned long long xp0 = pack2(xv.x, xv.y);
            unsigned long long xp1 = pack2(xv.z, xv.w);
            unsigned long long w0 = pack2(wv.x, wv.x);
            unsigned long long w1 = pack2(wv.y, wv.y);
            unsigned long long w2 = pack2(wv.z, wv.z);
            unsigned long long w3 = pack2(wv.w, wv.w);
            fma2(acc2[0][0], xp0, w0);
            fma2(acc2[0][1], xp0, w1);
            fma2(acc2[0][2], xp0, w2);
            fma2(acc2[0][3], xp0, w3);
            fma2(acc2[1][0], xp1, w0);
            fma2(acc2[1][1], xp1, w1);
            fma2(acc2[1][2], xp1, w2);
            fma2(acc2[1][3], xp1, w3);
        }
        __syncthreads();
    }

    // tail floats beyond 16B granularity (out_elems % 4)
    if (b == 0) {
        for (int i = (int)(n4 << 2) + tid; i < out_elems; i += GT) out[i] = 0.f;
    }

    // ---- logits -> smem (reuse pool as ls[BT][E+1], padded: conflict-free) ----
    float(*ls)[E + 1] = (float(*)[E + 1])pool;
#pragma unroll
    for (int p = 0; p < 2; p++)
#pragma unroll
        for (int j = 0; j < 4; j++) {
            float lo, hi;
            unpack2(acc2[p][j], lo, hi);
            ls[4 * ty + 2 * p + 0][4 * tx + j] = lo;
            ls[4 * ty + 2 * p + 1][4 * tx + j] = hi;
        }
    __syncthreads();

    // per-token softmax + argmax (first-max tie-break like jnp.argmax)
    if (tid < BT) {
        const int t = tid;
        float m = ls[t][0];
        int am = 0;
#pragma unroll
        for (int e = 1; e < E; e++) {
            float v = ls[t][e];
            if (v > m) { m = v; am = e; }
        }
        float ssum = 0.f;
#pragma unroll
        for (int e = 0; e < E; e++) ssum += expf(ls[t][e] - m);
        float inv = 1.0f / ssum;
        s_max[t] = m;
        s_inv[t] = inv;
        g_sel_gate[t0 + t] = inv;  // gate at argmax = exp(0)/sum
        g_sel_idx[t0 + t] = am;
    }
    __syncthreads();

    // per-expert partial column sums of gates (for me / l_aux)
    if (tid < E) {
        const int e = tid;
        float cs = 0.f;
#pragma unroll
        for (int t = 0; t < BT; t++) cs += expf(ls[t][e] - s_max[t]) * s_inv[t];
        g_me_part[b][e] = cs;
    }
}

// ---------------------------------------------------------------------------
// Per-expert: count assigned, exact 128th-largest-noise threshold (warp-0
// bitwise binary search, barrier-free), ordered block-scan to assign capacity
// slots, and direct scatter of combine/dispatch nonzeros.
// ---------------------------------------------------------------------------
#define BUF 5120
#define ETHREADS 256

__global__ __launch_bounds__(ETHREADS) void expert_kernel(
    const float* __restrict__ noise, float* __restrict__ out) {
    __shared__ uint32_t sbuf[BUF];
    __shared__ int scnt;
    __shared__ int sred;
    __shared__ uint32_t sV;
    __shared__ int swsum[ETHREADS / 32];

    const int e = blockIdx.x;
    const int tid = threadIdx.x;
    const int lane = tid & 31;
    const int wid = tid >> 5;

    if (tid == 0) {
        scnt = 0;
        sV = 0;
    }
    __syncthreads();

    // gather assigned noises into smem (order irrelevant for threshold)
    for (int t = tid; t < S; t += ETHREADS) {
        if (g_sel_idx[t] == e) {
            int p = atomicAdd(&scnt, 1);
            if (p < BUF) sbuf[p] = __float_as_uint(noise[(size_t)t * E + e]);
        }
    }
    __syncthreads();
    const int cnt = scnt;
    if (tid == 0) {
        g_cnt[e] = cnt;
        out[OFF_CNT + e] = (float)cnt;
    }

    // threshold V = bits of the CAP-th largest noise (kept iff bits >= V)
    if (cnt > CAP) {
        if (cnt <= BUF) {
            // warp 0 only: no block barriers in the 32-step search
            if (wid == 0) {
                uint32_t V = 0;
                for (int bit = 31; bit >= 0; bit--) {
                    uint32_t trial = V | (1u << bit);
                    int c = 0;
                    for (int i = lane; i < cnt; i += 32)
                        c += (sbuf[i] >= trial) ? 1 : 0;
#pragma unroll
                    for (int off = 16; off; off >>= 1)
                        c += __shfl_down_sync(0xffffffffu, c, off);
                    c = __shfl_sync(0xffffffffu, c, 0);
                    if (c >= CAP) V = trial;
                }
                if (lane == 0) sV = V;
            }
        } else {  // pathological skew fallback (never expected)
            uint32_t V = 0;
            for (int bit = 31; bit >= 0; bit--) {
                uint32_t trial = V | (1u << bit);
                int c = 0;
                for (int t = tid; t < S; t += ETHREADS)
                    c += (g_sel_idx[t] == e &&
                          __float_as_uint(noise[(size_t)t * E + e]) >= trial)
                             ? 1
                             : 0;
#pragma unroll
                for (int off = 16; off; off >>= 1)
                    c += __shfl_down_sync(0xffffffffu, c, off);
                __syncthreads();
                if (tid == 0) sred = 0;
                __syncthreads();
                if (lane == 0) atomicAdd(&sred, c);
                __syncthreads();
                if (sred >= CAP) V = trial;
            }
            if (tid == 0) sV = V;
        }
    }
    __syncthreads();
    const uint32_t V = sV;

    // ordered scan over tokens -> capacity slot; scatter outputs directly
    int running = 0;
    for (int base = 0; base < S; base += ETHREADS) {
        int t = base + tid;
        bool assigned = (g_sel_idx[t] == e);
        bool kept =
            assigned && (__float_as_uint(noise[(size_t)t * E + e]) >= V);
        unsigned m = __ballot_sync(0xffffffffu, kept);
        int pre = __popc(m & ((1u << lane) - 1u));
        if (lane == 0) swsum[wid] = __popc(m);
        __syncthreads();
        int wbase = 0;
#pragma unroll
        for (int ww = 0; ww < ETHREADS / 32; ww++) {
            if (ww < wid) wbase += swsum[ww];
        }
        int tot = 0;
#pragma unroll
        for (int ww = 0; ww < ETHREADS / 32; ww++) tot += swsum[ww];
        if (kept) {
            int slot = running + wbase + pre;
            size_t o = OFF_COMBINE + (((size_t)t * E + e) * CAP + (size_t)slot);
            out[o] = g_sel_gate[t];
            out[o + SEC] = 1.0f;
        }
        running += tot;
        __syncthreads();
    }
}

// ---------------------------------------------------------------------------
// l_aux: single tiny block.
// ---------------------------------------------------------------------------
__global__ __launch_bounds__(64) void laux_kernel(float* __restrict__ out) {
    __shared__ float red[2];
    const int tid = threadIdx.x;
    float ms = 0.f;
    for (int p = 0; p < NBLK; p++) ms += g_me_part[p][tid];
    float v = ms * (float)g_cnt[tid];
#pragma unroll
    for (int off = 16; off; off >>= 1)
        v += __shfl_down_sync(0xffffffffu, v, off);
    if (tid == 0) red[0] = v;
    if (tid == 32) red[1] = v;
    __syncthreads();
    if (tid == 0)
        out[0] = (red[0] + red[1]) * ((float)E / ((float)S * (float)S));
}

extern "C" void kernel_launch(void* const* d_in, const int* in_sizes, int n_in,
                              void* d_out, int out_size) {
    const float* x = (const float*)d_in[0];      // [S, D]
    const float* w = (const float*)d_in[1];      // [E, D]
    const float* noise = (const float*)d_in[2];  // [S, E]
    float* out = (float*)d_out;

    gate_gemm_kernel<<<NBLK, GT>>>(x, w, out, out_size);
    expert_kernel<<<E, ETHREADS>>>(noise, out);
    laux_kernel<<<1, 64>>>(out);
}

// round 7
// speedup vs baseline: 1.2223x; 1.0652x over previous
#include <cuda_runtime.h>
#include <stdint.h>

#define S 8192
#define D 4096
#define E 64
#define CAP 128

#define BT 64            // tokens per gemm block
#define KC 64            // k-chunk
#define GT 512           // gemm threads per block (16 warps/SM)
#define NBLK (S / BT)    // 128 gemm blocks = one wave on 152 SMs
#define NCHUNK (D / KC)  // 64

// output layout: [ l_aux (1) | combine (S*E*CAP) | dispatch (S*E*CAP) | exp_counts (E) ]
#define SEC ((size_t)S * E * CAP)
#define OFF_COMBINE ((size_t)1)
#define OFF_CNT ((size_t)1 + 2 * SEC)

// scratch (device globals: no allocation allowed)
__device__ float g_sel_gate[S];
__device__ int g_sel_idx[S];
__device__ float g_me_part[NBLK][E];
__device__ int g_cnt[E];

// ---- packed fp32x2 helpers ----
__device__ __forceinline__ void fma2(unsigned long long& d, unsigned long long a,
                                     unsigned long long b) {
    asm("fma.rn.f32x2 %0, %1, %2, %0;" : "+l"(d) : "l"(a), "l"(b));
}
__device__ __forceinline__ unsigned long long pack2(float lo, float hi) {
    unsigned long long r;
    asm("mov.b64 %0, {%1, %2};" : "=l"(r) : "f"(lo), "f"(hi));
    return r;
}
__device__ __forceinline__ void unpack2(unsigned long long v, float& lo, float& hi) {
    asm("mov.b64 {%0, %1}, %2;" : "=f"(lo), "=f"(hi) : "l"(v));
}

// ---------------------------------------------------------------------------
// Fused: gate GEMM (fp32, FFMA2) + softmax + argmax + per-expert gate-mean
//        partials + interleaved zero-fill of the output buffer.
// 512 threads (16 warps/SM, grid=128 = 1 block/SM), thread tile 2 tok x 4 exp.
// xs: token-major [tok][16 quads], quad-XOR swizzle (kkg ^ ((tok>>1)&7)).
// ws: kk-major   [kk][16 quads],  quad-XOR swizzle (txg ^ (kk>>2)).
// Every mainloop LDS.128 is ~1 wavefront; w reg-quad feeds FFMA2 directly.
// ---------------------------------------------------------------------------
__global__ __launch_bounds__(GT) void gate_gemm_kernel(
    const float* __restrict__ x, const float* __restrict__ w,
    float* __restrict__ out, int out_elems) {
    __shared__ float pool[KC * BT + KC * E];  // xs then ws; reused for logits
    __shared__ float s_max[BT];
    __shared__ float s_inv[BT];

    float* xs = pool;            // [BT][KC] swizzled, 4096 floats
    float* ws = pool + BT * KC;  // [KC][E]  swizzled, 4096 floats

    const int tid = threadIdx.x;
    const int b = blockIdx.x;
    const int lane = tid & 31;
    const int wid = tid >> 5;
    const int ty = (wid & 3) * 8 + (lane & 7);    // token-pair 0..31
    const int tx = (wid >> 2) * 4 + (lane >> 3);  // expert-quad 0..15
    const int t0 = b * BT;

    // ---- zero-fill bookkeeping ----
    const unsigned n4 = (unsigned)(out_elems >> 2);
    const unsigned per = (n4 + NBLK - 1) / NBLK;
    const unsigned z0 = (unsigned)b * per;
    const unsigned z1 = (z0 + per < n4) ? (z0 + per) : n4;
    float4* out4 = (float4*)out;
    const float4 zz = make_float4(0.f, 0.f, 0.f, 0.f);

    unsigned long long acc2[2][2];  // [token][expert-pair]
#pragma unroll
    for (int t = 0; t < 2; t++)
#pragma unroll
        for (int p = 0; p < 2; p++) acc2[t][p] = 0ull;

    float4 xr[2], wr[2];
    // prefetch chunk 0
#pragma unroll
    for (int l = 0; l < 2; l++) {
        int f4 = tid + l * GT;
        int row = f4 >> 4;
        int c4 = f4 & 15;
        xr[l] = *reinterpret_cast<const float4*>(&x[(size_t)(t0 + row) * D + c4 * 4]);
        wr[l] = *reinterpret_cast<const float4*>(&w[(size_t)row * D + c4 * 4]);
    }

    for (int ch = 0; ch < NCHUNK; ch++) {
        // ---- store regs -> swizzled smem ----
#pragma unroll
        for (int l = 0; l < 2; l++) {
            int f4 = tid + l * GT;
            int row = f4 >> 4;
            int c4 = f4 & 15;
            // x: token-major, quad q = row*16 + (c4 ^ ((row>>1)&7))
            int xq = row * 16 + (c4 ^ ((row >> 1) & 7));
            *reinterpret_cast<float4*>(&xs[xq * 4]) = xr[l];
            // w: kk-major, float (4c4+j)*64-region: quad = kk*16 + ((row>>2)^c4)
            float u[4] = {wr[l].x, wr[l].y, wr[l].z, wr[l].w};
#pragma unroll
            for (int j = 0; j < 4; j++) {
                int kk = 4 * c4 + j;
                int wq = kk * 16 + ((row >> 2) ^ c4);
                ws[wq * 4 + (row & 3)] = u[j];
            }
        }
        __syncthreads();

        // ---- prefetch next chunk ----
        if (ch + 1 < NCHUNK) {
            int kc = (ch + 1) * KC;
#pragma unroll
            for (int l = 0; l < 2; l++) {
                int f4 = tid + l * GT;
                int row = f4 >> 4;
                int c4 = f4 & 15;
                xr[l] = *reinterpret_cast<const float4*>(
                    &x[(size_t)(t0 + row) * D + kc + c4 * 4]);
                wr[l] = *reinterpret_cast<const float4*>(
                    &w[(size_t)row * D + kc + c4 * 4]);
            }
        }

        // ---- interleaved zero-fill slice (DRAM overlaps FMA) ----
#pragma unroll
        for (int k = 0; k < 9; k++) {
            unsigned idx = z0 + ((unsigned)ch * 9 + k) * GT + tid;
            if (idx < z1) out4[idx] = zz;
        }

        // ---- mainloop ----
#pragma unroll
        for (int kkg = 0; kkg < 16; kkg++) {
            int xsw = kkg ^ (ty & 7);
            float4 xe = *reinterpret_cast<const float4*>(
                &xs[((2 * ty) * 16 + xsw) * 4]);
            float4 xo = *reinterpret_cast<const float4*>(
                &xs[((2 * ty + 1) * 16 + xsw) * 4]);
            float xea[4] = {xe.x, xe.y, xe.z, xe.w};
            float xoa[4] = {xo.x, xo.y, xo.z, xo.w};
#pragma unroll
            for (int j = 0; j < 4; j++) {
                int kk = kkg * 4 + j;
                float4 wv = *reinterpret_cast<const float4*>(
                    &ws[(kk * 16 + (tx ^ kkg)) * 4]);
                unsigned long long wp0 = pack2(wv.x, wv.y);
                unsigned long long wp1 = pack2(wv.z, wv.w);
                unsigned long long xd0 = pack2(xea[j], xea[j]);
                unsigned long long xd1 = pack2(xoa[j], xoa[j]);
                fma2(acc2[0][0], wp0, xd0);
                fma2(acc2[0][1], wp1, xd0);
                fma2(acc2[1][0], wp0, xd1);
                fma2(acc2[1][1], wp1, xd1);
            }
        }
        __syncthreads();
    }

    // tail floats beyond 16B granularity
    if (b == 0) {
        for (int i = (int)(n4 << 2) + tid; i < out_elems; i += GT) out[i] = 0.f;
    }

    // ---- logits -> smem (reuse pool as ls[BT][E+1]) ----
    float(*ls)[E + 1] = (float(*)[E + 1])pool;
#pragma unroll
    for (int t = 0; t < 2; t++)
#pragma unroll
        for (int p = 0; p < 2; p++) {
            float lo, hi;
            unpack2(acc2[t][p], lo, hi);
            ls[2 * ty + t][4 * tx + 2 * p + 0] = lo;
            ls[2 * ty + t][4 * tx + 2 * p + 1] = hi;
        }
    __syncthreads();

    // per-token softmax + argmax (first-max tie-break like jnp.argmax)
    if (tid < BT) {
        const int t = tid;
        float m = ls[t][0];
        int am = 0;
#pragma unroll
        for (int e = 1; e < E; e++) {
            float v = ls[t][e];
            if (v > m) { m = v; am = e; }
        }
        float ssum = 0.f;
#pragma unroll
        for (int e = 0; e < E; e++) ssum += expf(ls[t][e] - m);
        float inv = 1.0f / ssum;
        s_max[t] = m;
        s_inv[t] = inv;
        g_sel_gate[t0 + t] = inv;  // gate at argmax = exp(0)/sum
        g_sel_idx[t0 + t] = am;
    }
    __syncthreads();

    // per-expert partial column sums of gates (for me / l_aux)
    if (tid < E) {
        const int e = tid;
        float cs = 0.f;
#pragma unroll
        for (int t = 0; t < BT; t++) cs += expf(ls[t][e] - s_max[t]) * s_inv[t];
        g_me_part[b][e] = cs;
    }
}

// ---------------------------------------------------------------------------
// Per-expert: count assigned, exact 128th-largest-noise threshold (warp-0
// bitwise binary search), ordered block-scan slot assignment, direct scatter.
// ---------------------------------------------------------------------------
#define BUF 5120
#define ETHREADS 256

__global__ __launch_bounds__(ETHREADS) void expert_kernel(
    const float* __restrict__ noise, float* __restrict__ out) {
    __shared__ uint32_t sbuf[BUF];
    __shared__ int scnt;
    __shared__ int sred;
    __shared__ uint32_t sV;
    __shared__ int swsum[ETHREADS / 32];

    const int e = blockIdx.x;
    const int tid = threadIdx.x;
    const int lane = tid & 31;
    const int wid = tid >> 5;

    if (tid == 0) {
        scnt = 0;
        sV = 0;
    }
    __syncthreads();

    for (int t = tid; t < S; t += ETHREADS) {
        if (g_sel_idx[t] == e) {
            int p = atomicAdd(&scnt, 1);
            if (p < BUF) sbuf[p] = __float_as_uint(noise[(size_t)t * E + e]);
        }
    }
    __syncthreads();
    const int cnt = scnt;
    if (tid == 0) {
        g_cnt[e] = cnt;
        out[OFF_CNT + e] = (float)cnt;
    }

    if (cnt > CAP) {
        if (cnt <= BUF) {
            if (wid == 0) {
                uint32_t V = 0;
                for (int bit = 31; bit >= 0; bit--) {
                    uint32_t trial = V | (1u << bit);
                    int c = 0;
                    for (int i = lane; i < cnt; i += 32)
                        c += (sbuf[i] >= trial) ? 1 : 0;
#pragma unroll
                    for (int off = 16; off; off >>= 1)
                        c += __shfl_down_sync(0xffffffffu, c, off);
                    c = __shfl_sync(0xffffffffu, c, 0);
                    if (c >= CAP) V = trial;
                }
                if (lane == 0) sV = V;
            }
        } else {  // pathological skew fallback
            uint32_t V = 0;
            for (int bit = 31; bit >= 0; bit--) {
                uint32_t trial = V | (1u << bit);
                int c = 0;
                for (int t = tid; t < S; t += ETHREADS)
                    c += (g_sel_idx[t] == e &&
                          __float_as_uint(noise[(size_t)t * E + e]) >= trial)
                             ? 1
                             : 0;
#pragma unroll
                for (int off = 16; off; off >>= 1)
                    c += __shfl_down_sync(0xffffffffu, c, off);
                __syncthreads();
                if (tid == 0) sred = 0;
                __syncthreads();
                if (lane == 0) atomicAdd(&sred, c);
                __syncthreads();
                if (sred >= CAP) V = trial;
            }
            if (tid == 0) sV = V;
        }
    }
    __syncthreads();
    const uint32_t V = sV;

    int running = 0;
    for (int base = 0; base < S; base += ETHREADS) {
        int t = base + tid;
        bool assigned = (g_sel_idx[t] == e);
        bool kept =
            assigned && (__float_as_uint(noise[(size_t)t * E + e]) >= V);
        unsigned m = __ballot_sync(0xffffffffu, kept);
        int pre = __popc(m & ((1u << lane) - 1u));
        if (lane == 0) swsum[wid] = __popc(m);
        __syncthreads();
        int wbase = 0;
#pragma unroll
        for (int ww = 0; ww < ETHREADS / 32; ww++) {
            if (ww < wid) wbase += swsum[ww];
        }
        int tot = 0;
#pragma unroll
        for (int ww = 0; ww < ETHREADS / 32; ww++) tot += swsum[ww];
        if (kept) {
            int slot = running + wbase + pre;
            size_t o = OFF_COMBINE + (((size_t)t * E + e) * CAP + (size_t)slot);
            out[o] = g_sel_gate[t];
            out[o + SEC] = 1.0f;
        }
        running += tot;
        __syncthreads();
    }
}

__global__ __launch_bounds__(64) void laux_kernel(float* __restrict__ out) {
    __shared__ float red[2];
    const int tid = threadIdx.x;
    float ms = 0.f;
    for (int p = 0; p < NBLK; p++) ms += g_me_part[p][tid];
    float v = ms * (float)g_cnt[tid];
#pragma unroll
    for (int off = 16; off; off >>= 1)
        v += __shfl_down_sync(0xffffffffu, v, off);
    if (tid == 0) red[0] = v;
    if (tid == 32) red[1] = v;
    __syncthreads();
    if (tid == 0)
        out[0] = (red[0] + red[1]) * ((float)E / ((float)S * (float)S));
}

extern "C" void kernel_launch(void* const* d_in, const int* in_sizes, int n_in,
                              void* d_out, int out_size) {
    const float* x = (const float*)d_in[0];      // [S, D]
    const float* w = (const float*)d_in[1];      // [E, D]
    const float* noise = (const float*)d_in[2];  // [S, E]
    float* out = (float*)d_out;

    gate_gemm_kernel<<<NBLK, GT>>>(x, w, out, out_size);
    expert_kernel<<<E, ETHREADS>>>(noise, out);
    laux_kernel<<<1, 64>>>(out);
}